// round 2
// baseline (speedup 1.0000x reference)
#include <cuda_runtime.h>
#include <math.h>

// Problem constants (fixed shapes from reference)
#define E_      32
#define KSEL    4
#define H_      1024
#define IDIM    768
#define T_      4096
#define NGROUP  8
#define TOPKG   4
#define CAP     1024
#define NASSIGN (T_ * KSEL)

// GEMM tiling
#define BM 64
#define BN 64
#define BK 16

// ---------------- scratch (device globals; no allocations) ----------------
__device__ float g_buf[(size_t)E_ * CAP * H_];     // gathered token rows per expert
__device__ float g_act[(size_t)E_ * CAP * IDIM];   // silu(h1)*h3
__device__ float g_y  [(size_t)E_ * CAP * H_];     // expert outputs
__device__ int   g_cnt [E_];
__device__ int   g_tok [E_ * CAP];                 // token id per (expert, slot)
__device__ int   g_expi[NASSIGN];                  // expert per assignment (flat t*K+k)
__device__ int   g_slot[NASSIGN];                  // slot per assignment (-1 = dropped)
__device__ float g_gw  [NASSIGN];                  // normalized gate weight

// ---------------- kernels ----------------

// One block per token, 128 threads. DeepSeek-v3 group-limited sigmoid routing.
// Tie-breaking matches jax.lax.top_k (stable: lower index wins) via strict->.
// Writes expert choice + weight per assignment; slots assigned later in
// deterministic token order (matches reference's stable argsort + capacity drop).
__global__ void router_kernel(const float* __restrict__ x,
                              const float* __restrict__ gate_w,
                              const float* __restrict__ bias) {
    __shared__ float xs[H_];
    __shared__ float sc[E_];
    int t   = blockIdx.x;
    int tid = threadIdx.x;

    const float4* xr  = (const float4*)(x + (size_t)t * H_);
    float4*       xs4 = (float4*)xs;
    for (int i = tid; i < H_ / 4; i += 128) xs4[i] = xr[i];
    __syncthreads();

    int warp = tid >> 5, lane = tid & 31;
    for (int e8 = 0; e8 < 8; e8++) {
        int e = warp * 8 + e8;
        const float* g = gate_w + (size_t)e * H_;
        float p = 0.f;
        for (int h = lane; h < H_; h += 32) p += xs[h] * g[h];
        #pragma unroll
        for (int o = 16; o; o >>= 1) p += __shfl_xor_sync(0xffffffffu, p, o);
        if (lane == 0) sc[e] = p;
    }
    __syncthreads();

    if (tid == 0) {
        float s[E_], sfc[E_];
        #pragma unroll
        for (int e = 0; e < E_; e++) {
            s[e]   = 1.f / (1.f + expf(-sc[e]));
            sfc[e] = s[e] + bias[e];
        }
        // group scores = sum of top-2 within each group of 4
        float gs[NGROUP];
        #pragma unroll
        for (int g = 0; g < NGROUP; g++) {
            float m1 = -1e30f, m2 = -1e30f;
            #pragma unroll
            for (int j = 0; j < 4; j++) {
                float v = sfc[g * 4 + j];
                if (v > m1) { m2 = m1; m1 = v; }
                else if (v > m2) m2 = v;
            }
            gs[g] = m1 + m2;
        }
        // top-4 groups
        bool gsel[NGROUP];
        #pragma unroll
        for (int g = 0; g < NGROUP; g++) gsel[g] = false;
        for (int it = 0; it < TOPKG; it++) {
            float best = -1e30f; int bi = 0;
            #pragma unroll
            for (int g = 0; g < NGROUP; g++)
                if (!gsel[g] && gs[g] > best) { best = gs[g]; bi = g; }
            gsel[bi] = true;
        }
        // top-4 experts among selected groups
        float tmp[E_];
        #pragma unroll
        for (int e = 0; e < E_; e++) tmp[e] = gsel[e >> 2] ? sfc[e] : 0.f;
        int sel[KSEL];
        for (int k = 0; k < KSEL; k++) {
            float best = -1e30f; int bi = 0;
            #pragma unroll
            for (int e = 0; e < E_; e++)
                if (tmp[e] > best) { best = tmp[e]; bi = e; }
            sel[k] = bi; tmp[bi] = -1e30f;
        }
        float rw[KSEL], rs = 0.f;
        #pragma unroll
        for (int k = 0; k < KSEL; k++) { rw[k] = s[sel[k]]; rs += rw[k]; }
        float inv = 1.f / rs;
        #pragma unroll
        for (int k = 0; k < KSEL; k++) {
            int a = t * KSEL + k;
            g_expi[a] = sel[k];
            g_gw[a]   = rw[k] * inv;
        }
    }
}

// Deterministic slot assignment: slot = rank of this assignment among all
// assignments to the same expert, in flat (token, k) order. Exactly matches
// the reference's stable argsort + exclusive-prefix position. One block per
// expert, 1024 threads, ballot-based block prefix sum over 16 chunks.
__global__ __launch_bounds__(1024) void slot_kernel() {
    int e   = blockIdx.x;
    int tid = threadIdx.x;
    int lane = tid & 31, warp = tid >> 5;
    __shared__ int warp_sums[32];

    int base = 0;
    for (int c0 = 0; c0 < NASSIGN; c0 += 1024) {
        int a = c0 + tid;
        bool flag = (g_expi[a] == e);
        unsigned bal = __ballot_sync(0xffffffffu, flag);
        int wprefix = __popc(bal & ((1u << lane) - 1u));
        if (lane == 31) warp_sums[warp] = __popc(bal);
        __syncthreads();
        if (warp == 0) {
            int v = warp_sums[lane];
            #pragma unroll
            for (int o = 1; o < 32; o <<= 1) {
                int n = __shfl_up_sync(0xffffffffu, v, o);
                if (lane >= o) v += n;
            }
            warp_sums[lane] = v;  // inclusive scan
        }
        __syncthreads();
        int woff  = (warp == 0) ? 0 : warp_sums[warp - 1];
        int total = warp_sums[31];
        if (flag) {
            int slot = base + woff + wprefix;
            if (slot < CAP) {
                g_slot[a] = slot;
                g_tok[e * CAP + slot] = a >> 2;  // token id
            } else {
                g_slot[a] = -1;  // capacity drop -> weight 0 (matches reference)
            }
        }
        base += total;
        __syncthreads();
    }
    if (tid == 0) g_cnt[e] = base < CAP ? base : CAP;
}

// Copy token rows into per-expert contiguous buffers.
__global__ void gather_kernel(const float* __restrict__ x) {
    int e = blockIdx.y, slot = blockIdx.x;
    if (slot >= g_cnt[e]) return;
    int t = g_tok[e * CAP + slot];
    const float4* src = (const float4*)(x + (size_t)t * H_);
    float4*       dst = (float4*)(g_buf + ((size_t)e * CAP + slot) * H_);
    for (int i = threadIdx.x; i < H_ / 4; i += blockDim.x) dst[i] = src[i];
}

// GEMM1: act = silu(X @ w1^T) * (X @ w3^T), per expert. All K-major (H contiguous).
__global__ __launch_bounds__(256) void gemm1_kernel(const float* __restrict__ w1,
                                                    const float* __restrict__ w3) {
    int e = blockIdx.z;
    int cnt = g_cnt[e];
    int m0 = blockIdx.y * BM;
    if (m0 >= cnt) return;
    int n0 = blockIdx.x * BN;

    __shared__ float As [BK][BM + 4];
    __shared__ float B1s[BK][BN + 4];
    __shared__ float B3s[BK][BN + 4];

    int tid = threadIdx.x;
    int tx = tid & 15, ty = tid >> 4;
    int lk = (tid & 3) * 4, lm = tid >> 2;

    const float* A  = g_buf + ((size_t)e * CAP  + m0) * H_;
    const float* B1 = w1    + ((size_t)e * IDIM + n0) * H_;
    const float* B3 = w3    + ((size_t)e * IDIM + n0) * H_;

    float acc1[4][4] = {}, acc3[4][4] = {};

    for (int k0 = 0; k0 < H_; k0 += BK) {
        float4 av  = *(const float4*)(A  + (size_t)lm * H_ + k0 + lk);
        float4 b1v = *(const float4*)(B1 + (size_t)lm * H_ + k0 + lk);
        float4 b3v = *(const float4*)(B3 + (size_t)lm * H_ + k0 + lk);
        __syncthreads();
        As [lk + 0][lm] = av.x;  As [lk + 1][lm] = av.y;
        As [lk + 2][lm] = av.z;  As [lk + 3][lm] = av.w;
        B1s[lk + 0][lm] = b1v.x; B1s[lk + 1][lm] = b1v.y;
        B1s[lk + 2][lm] = b1v.z; B1s[lk + 3][lm] = b1v.w;
        B3s[lk + 0][lm] = b3v.x; B3s[lk + 1][lm] = b3v.y;
        B3s[lk + 2][lm] = b3v.z; B3s[lk + 3][lm] = b3v.w;
        __syncthreads();
        #pragma unroll
        for (int k = 0; k < BK; k++) {
            float4 a4  = *(const float4*)&As [k][ty * 4];
            float4 b14 = *(const float4*)&B1s[k][tx * 4];
            float4 b34 = *(const float4*)&B3s[k][tx * 4];
            float a[4]  = {a4.x, a4.y, a4.z, a4.w};
            float b1[4] = {b14.x, b14.y, b14.z, b14.w};
            float b3[4] = {b34.x, b34.y, b34.z, b34.w};
            #pragma unroll
            for (int i = 0; i < 4; i++)
                #pragma unroll
                for (int j = 0; j < 4; j++) {
                    acc1[i][j] += a[i] * b1[j];
                    acc3[i][j] += a[i] * b3[j];
                }
        }
    }

    float* outp = g_act + (size_t)e * CAP * IDIM;
    #pragma unroll
    for (int i = 0; i < 4; i++) {
        int row = m0 + ty * 4 + i;
        float4 o;
        float* po = (float*)&o;
        #pragma unroll
        for (int j = 0; j < 4; j++) {
            float h1 = acc1[i][j];
            float sg = 1.f / (1.f + expf(-h1));
            po[j] = h1 * sg * acc3[i][j];
        }
        *(float4*)(outp + (size_t)row * IDIM + n0 + tx * 4) = o;
    }
}

// GEMM2: y = act @ w2^T per expert.
__global__ __launch_bounds__(256) void gemm2_kernel(const float* __restrict__ w2) {
    int e = blockIdx.z;
    int cnt = g_cnt[e];
    int m0 = blockIdx.y * BM;
    if (m0 >= cnt) return;
    int n0 = blockIdx.x * BN;

    __shared__ float As[BK][BM + 4];
    __shared__ float Bs[BK][BN + 4];

    int tid = threadIdx.x;
    int tx = tid & 15, ty = tid >> 4;
    int lk = (tid & 3) * 4, lm = tid >> 2;

    const float* A = g_act + ((size_t)e * CAP + m0) * IDIM;
    const float* B = w2    + ((size_t)e * H_  + n0) * IDIM;

    float acc[4][4] = {};

    for (int k0 = 0; k0 < IDIM; k0 += BK) {
        float4 av = *(const float4*)(A + (size_t)lm * IDIM + k0 + lk);
        float4 bv = *(const float4*)(B + (size_t)lm * IDIM + k0 + lk);
        __syncthreads();
        As[lk + 0][lm] = av.x; As[lk + 1][lm] = av.y;
        As[lk + 2][lm] = av.z; As[lk + 3][lm] = av.w;
        Bs[lk + 0][lm] = bv.x; Bs[lk + 1][lm] = bv.y;
        Bs[lk + 2][lm] = bv.z; Bs[lk + 3][lm] = bv.w;
        __syncthreads();
        #pragma unroll
        for (int k = 0; k < BK; k++) {
            float4 a4 = *(const float4*)&As[k][ty * 4];
            float4 b4 = *(const float4*)&Bs[k][tx * 4];
            float a[4] = {a4.x, a4.y, a4.z, a4.w};
            float b[4] = {b4.x, b4.y, b4.z, b4.w};
            #pragma unroll
            for (int i = 0; i < 4; i++)
                #pragma unroll
                for (int j = 0; j < 4; j++)
                    acc[i][j] += a[i] * b[j];
        }
    }

    float* outp = g_y + (size_t)e * CAP * H_;
    #pragma unroll
    for (int i = 0; i < 4; i++) {
        int row = m0 + ty * 4 + i;
        float4 o = make_float4(acc[i][0], acc[i][1], acc[i][2], acc[i][3]);
        *(float4*)(outp + (size_t)row * H_ + n0 + tx * 4) = o;
    }
}

// Final combine: out[t] = sum_k w[t,k] * y[expert(t,k), slot(t,k)]. No atomics.
__global__ void combine_kernel(float* __restrict__ out) {
    int t = blockIdx.x;
    int i = threadIdx.x;  // 256 threads, float4 lanes over H
    float4 acc = make_float4(0.f, 0.f, 0.f, 0.f);
    #pragma unroll
    for (int k = 0; k < KSEL; k++) {
        int a = t * KSEL + k;
        int slot = g_slot[a];
        if (slot < 0) continue;
        int e = g_expi[a];
        float w = g_gw[a];
        const float4* yr = (const float4*)(g_y + ((size_t)e * CAP + slot) * H_);
        float4 v = yr[i];
        acc.x += w * v.x; acc.y += w * v.y; acc.z += w * v.z; acc.w += w * v.w;
    }
    ((float4*)(out + (size_t)t * H_))[i] = acc;
}

// ---------------- launch ----------------
extern "C" void kernel_launch(void* const* d_in, const int* in_sizes, int n_in,
                              void* d_out, int out_size) {
    (void)in_sizes; (void)n_in; (void)out_size;
    const float* x      = (const float*)d_in[0];
    const float* gate_w = (const float*)d_in[1];
    const float* w1     = (const float*)d_in[2];
    const float* w3     = (const float*)d_in[3];
    const float* w2     = (const float*)d_in[4];
    const float* bias   = (const float*)d_in[5];
    float*       out    = (float*)d_out;

    router_kernel<<<T_, 128>>>(x, gate_w, bias);
    slot_kernel<<<E_, 1024>>>();
    gather_kernel<<<dim3(CAP, E_), 256>>>(x);
    gemm1_kernel<<<dim3(IDIM / BN, CAP / BM, E_), 256>>>(w1, w3);
    gemm2_kernel<<<dim3(H_ / BN, CAP / BM, E_), 256>>>(w2);
    combine_kernel<<<T_, 256>>>(out);
}

// round 4
// speedup vs baseline: 1.8476x; 1.8476x over previous
#include <cuda_runtime.h>
#include <cuda_bf16.h>
#include <math.h>
#include <stdint.h>

#define E_      32
#define KSEL    4
#define H_      1024
#define IDIM    768
#define T_      4096
#define NGROUP  8
#define TOPKG   4
#define CAP     1024
#define NASSIGN (T_ * KSEL)

// ---------------- scratch (device globals; no allocations) ----------------
__device__ __nv_bfloat16 g_bufh[(size_t)E_ * CAP * H_];
__device__ __nv_bfloat16 g_bufl[(size_t)E_ * CAP * H_];
__device__ __nv_bfloat16 g_acth[(size_t)E_ * CAP * IDIM];
__device__ __nv_bfloat16 g_actl[(size_t)E_ * CAP * IDIM];
__device__ __nv_bfloat16 g_w1h[(size_t)E_ * IDIM * H_];
__device__ __nv_bfloat16 g_w1l[(size_t)E_ * IDIM * H_];
__device__ __nv_bfloat16 g_w3h[(size_t)E_ * IDIM * H_];
__device__ __nv_bfloat16 g_w3l[(size_t)E_ * IDIM * H_];
__device__ __nv_bfloat16 g_w2h[(size_t)E_ * H_ * IDIM];
__device__ __nv_bfloat16 g_w2l[(size_t)E_ * H_ * IDIM];
__device__ float g_y[(size_t)E_ * CAP * H_];
__device__ int   g_cnt [E_];
__device__ int   g_tok [E_ * CAP];
__device__ int   g_expi[NASSIGN];
__device__ int   g_slot[NASSIGN];
__device__ float g_gw  [NASSIGN];

// ---------------- helpers ----------------
__device__ __forceinline__ uint32_t smem_u32(const void* p) {
    uint32_t a;
    asm("{ .reg .u64 t; cvta.to.shared.u64 t, %1; cvt.u32.u64 %0, t; }" : "=r"(a) : "l"(p));
    return a;
}
__device__ __forceinline__ void cp16(uint32_t dst, const void* src) {
    asm volatile("cp.async.cg.shared.global [%0], [%1], 16;" :: "r"(dst), "l"(src));
}
__device__ __forceinline__ void cp_commit() { asm volatile("cp.async.commit_group;"); }
__device__ __forceinline__ void cp_wait1()  { asm volatile("cp.async.wait_group 1;"); }
__device__ __forceinline__ uint32_t lds32(uint32_t a) {
    uint32_t v;
    asm volatile("ld.shared.b32 %0, [%1];" : "=r"(v) : "r"(a));
    return v;
}
__device__ __forceinline__ void mma16816(float* c, uint32_t a0, uint32_t a1, uint32_t a2,
                                         uint32_t a3, uint32_t b0, uint32_t b1) {
    asm volatile(
        "mma.sync.aligned.m16n8k16.row.col.f32.bf16.bf16.f32 "
        "{%0,%1,%2,%3}, {%4,%5,%6,%7}, {%8,%9}, {%0,%1,%2,%3};"
        : "+f"(c[0]), "+f"(c[1]), "+f"(c[2]), "+f"(c[3])
        : "r"(a0), "r"(a1), "r"(a2), "r"(a3), "r"(b0), "r"(b1));
}
// split two fp32 into packed bf16x2 hi + lo planes
__device__ __forceinline__ void split2(float x, float y, uint32_t& h, uint32_t& l) {
    __nv_bfloat16 hx = __float2bfloat16(x), hy = __float2bfloat16(y);
    float rx = x - __bfloat162float(hx), ry = y - __bfloat162float(hy);
    __nv_bfloat16 lx = __float2bfloat16(rx), ly = __float2bfloat16(ry);
    h = (uint32_t)__bfloat16_as_ushort(hx) | ((uint32_t)__bfloat16_as_ushort(hy) << 16);
    l = (uint32_t)__bfloat16_as_ushort(lx) | ((uint32_t)__bfloat16_as_ushort(ly) << 16);
}

// ---------------- weight conversion ----------------
__global__ void cvt_kernel(const float4* __restrict__ src, uint2* __restrict__ hi,
                           uint2* __restrict__ lo, int n4) {
    for (int i = blockIdx.x * blockDim.x + threadIdx.x; i < n4; i += gridDim.x * blockDim.x) {
        float4 v = src[i];
        uint32_t h0, l0, h1, l1;
        split2(v.x, v.y, h0, l0);
        split2(v.z, v.w, h1, l1);
        hi[i] = make_uint2(h0, h1);
        lo[i] = make_uint2(l0, l1);
    }
}

// ---------------- router / dispatch (verified exact) ----------------
__global__ void router_kernel(const float* __restrict__ x,
                              const float* __restrict__ gate_w,
                              const float* __restrict__ bias) {
    __shared__ float xs[H_];
    __shared__ float sc[E_];
    int t = blockIdx.x, tid = threadIdx.x;
    const float4* xr  = (const float4*)(x + (size_t)t * H_);
    float4*       xs4 = (float4*)xs;
    for (int i = tid; i < H_ / 4; i += 128) xs4[i] = xr[i];
    __syncthreads();
    int warp = tid >> 5, lane = tid & 31;
    for (int e8 = 0; e8 < 8; e8++) {
        int e = warp * 8 + e8;
        const float* g = gate_w + (size_t)e * H_;
        float p = 0.f;
        for (int h = lane; h < H_; h += 32) p += xs[h] * g[h];
        #pragma unroll
        for (int o = 16; o; o >>= 1) p += __shfl_xor_sync(0xffffffffu, p, o);
        if (lane == 0) sc[e] = p;
    }
    __syncthreads();
    if (tid == 0) {
        float s[E_], sfc[E_];
        #pragma unroll
        for (int e = 0; e < E_; e++) {
            s[e]   = 1.f / (1.f + expf(-sc[e]));
            sfc[e] = s[e] + bias[e];
        }
        float gs[NGROUP];
        #pragma unroll
        for (int g = 0; g < NGROUP; g++) {
            float m1 = -1e30f, m2 = -1e30f;
            #pragma unroll
            for (int j = 0; j < 4; j++) {
                float v = sfc[g * 4 + j];
                if (v > m1) { m2 = m1; m1 = v; }
                else if (v > m2) m2 = v;
            }
            gs[g] = m1 + m2;
        }
        bool gsel[NGROUP];
        #pragma unroll
        for (int g = 0; g < NGROUP; g++) gsel[g] = false;
        for (int it = 0; it < TOPKG; it++) {
            float best = -1e30f; int bi = 0;
            #pragma unroll
            for (int g = 0; g < NGROUP; g++)
                if (!gsel[g] && gs[g] > best) { best = gs[g]; bi = g; }
            gsel[bi] = true;
        }
        float tmp[E_];
        #pragma unroll
        for (int e = 0; e < E_; e++) tmp[e] = gsel[e >> 2] ? sfc[e] : 0.f;
        int sel[KSEL];
        for (int k = 0; k < KSEL; k++) {
            float best = -1e30f; int bi = 0;
            #pragma unroll
            for (int e = 0; e < E_; e++)
                if (tmp[e] > best) { best = tmp[e]; bi = e; }
            sel[k] = bi; tmp[bi] = -1e30f;
        }
        float rw[KSEL], rs = 0.f;
        #pragma unroll
        for (int k = 0; k < KSEL; k++) { rw[k] = s[sel[k]]; rs += rw[k]; }
        float inv = 1.f / rs;
        #pragma unroll
        for (int k = 0; k < KSEL; k++) {
            int a = t * KSEL + k;
            g_expi[a] = sel[k];
            g_gw[a]   = rw[k] * inv;
        }
    }
}

__global__ __launch_bounds__(1024) void slot_kernel() {
    int e = blockIdx.x, tid = threadIdx.x;
    int lane = tid & 31, warp = tid >> 5;
    __shared__ int warp_sums[32];
    int base = 0;
    for (int c0 = 0; c0 < NASSIGN; c0 += 1024) {
        int a = c0 + tid;
        bool flag = (g_expi[a] == e);
        unsigned bal = __ballot_sync(0xffffffffu, flag);
        int wprefix = __popc(bal & ((1u << lane) - 1u));
        if (lane == 31) warp_sums[warp] = __popc(bal);
        __syncthreads();
        if (warp == 0) {
            int v = warp_sums[lane];
            #pragma unroll
            for (int o = 1; o < 32; o <<= 1) {
                int n = __shfl_up_sync(0xffffffffu, v, o);
                if (lane >= o) v += n;
            }
            warp_sums[lane] = v;
        }
        __syncthreads();
        int woff  = (warp == 0) ? 0 : warp_sums[warp - 1];
        int total = warp_sums[31];
        if (flag) {
            int slot = base + woff + wprefix;
            if (slot < CAP) {
                g_slot[a] = slot;
                g_tok[e * CAP + slot] = a >> 2;
            } else {
                g_slot[a] = -1;
            }
        }
        base += total;
        __syncthreads();
    }
    if (tid == 0) g_cnt[e] = base < CAP ? base : CAP;
}

// gather: write token rows as bf16 hi/lo planes
__global__ void gather_kernel(const float* __restrict__ x) {
    int e = blockIdx.y, slot = blockIdx.x;
    if (slot >= g_cnt[e]) return;
    int t = g_tok[e * CAP + slot];
    const float4* src = (const float4*)(x + (size_t)t * H_);
    uint2* dh = (uint2*)(g_bufh + ((size_t)e * CAP + slot) * H_);
    uint2* dl = (uint2*)(g_bufl + ((size_t)e * CAP + slot) * H_);
    for (int i = threadIdx.x; i < H_ / 4; i += blockDim.x) {
        float4 v = src[i];
        uint32_t h0, l0, h1, l1;
        split2(v.x, v.y, h0, l0);
        split2(v.z, v.w, h1, l1);
        dh[i] = make_uint2(h0, h1);
        dl[i] = make_uint2(l0, l1);
    }
}

// ---------------- GEMM common constants ----------------
#define SROW   80          // smem bytes per 32-bf16 row (padded, conflict-free)
#define PS     (128 * SROW)  // plane size = 10240 B

// ---------------- GEMM1: fused h1/h3 + SiLU, 3-pass bf16 mma ----------------
#define G1_PLANES 6
#define G1_STAGE  (G1_PLANES * PS)   // 61440
#define G1_SMEM   (3 * G1_STAGE)     // 184320

__global__ __launch_bounds__(256) void gemm1_mma(void) {
    int e   = blockIdx.z;
    int cnt = g_cnt[e];
    int m0  = blockIdx.y * 128;
    if (m0 >= cnt) return;
    int n0  = blockIdx.x * 128;

    extern __shared__ char sm[];
    uint32_t sb = smem_u32(sm);
    int tid = threadIdx.x, lane = tid & 31, wid = tid >> 5;
    int wm = (wid & 1) * 64, wn = (wid >> 1) * 32;
    int g = lane >> 2, tg = lane & 3;

    const __nv_bfloat16* srcs[G1_PLANES] = {
        g_bufh + ((size_t)e * CAP  + m0) * H_,
        g_bufl + ((size_t)e * CAP  + m0) * H_,
        g_w1h  + ((size_t)e * IDIM + n0) * H_,
        g_w1l  + ((size_t)e * IDIM + n0) * H_,
        g_w3h  + ((size_t)e * IDIM + n0) * H_,
        g_w3l  + ((size_t)e * IDIM + n0) * H_
    };
    int  lrow = tid >> 1;                 // 0..127
    int  lcb  = (tid & 1) * 2;            // chunk base 0 or 2
    uint32_t ldst = lrow * SROW + lcb * 16;

    // prologue: stages 0,1
    #pragma unroll
    for (int st = 0; st < 2; st++) {
        uint32_t s = sb + st * G1_STAGE + ldst;
        int k0 = st * 32 + lcb * 8;
        #pragma unroll
        for (int p = 0; p < G1_PLANES; p++) {
            const __nv_bfloat16* gp = srcs[p] + (size_t)lrow * H_ + k0;
            cp16(s + p * PS,      gp);
            cp16(s + p * PS + 16, gp + 8);
        }
        cp_commit();
    }

    float c1[4][4][4] = {}, c3[4][4][4] = {};
    uint32_t aoff = (wm + g) * SROW + tg * 4;
    uint32_t boff = (wn + g) * SROW + tg * 4;

    const int NK = H_ / 32;  // 32
    for (int kt = 0; kt < NK; kt++) {
        cp_wait1();
        __syncthreads();
        if (kt + 2 < NK) {
            uint32_t s = sb + ((kt + 2) % 3) * G1_STAGE + ldst;
            int k0 = (kt + 2) * 32 + lcb * 8;
            #pragma unroll
            for (int p = 0; p < G1_PLANES; p++) {
                const __nv_bfloat16* gp = srcs[p] + (size_t)lrow * H_ + k0;
                cp16(s + p * PS,      gp);
                cp16(s + p * PS + 16, gp + 8);
            }
        }
        cp_commit();

        uint32_t bs = sb + (kt % 3) * G1_STAGE;
        #pragma unroll
        for (int kb = 0; kb < 2; kb++) {
            uint32_t ko = kb * 32;
            #pragma unroll
            for (int p = 0; p < 3; p++) {
                uint32_t ap = (p == 1) ? PS : 0;
                uint32_t bp = (p == 2) ? PS : 0;
                uint32_t a_[4][4];
                #pragma unroll
                for (int mi = 0; mi < 4; mi++) {
                    uint32_t ba = bs + ap + aoff + mi * (16 * SROW) + ko;
                    a_[mi][0] = lds32(ba);
                    a_[mi][1] = lds32(ba + 8 * SROW);
                    a_[mi][2] = lds32(ba + 16);
                    a_[mi][3] = lds32(ba + 8 * SROW + 16);
                }
                uint32_t b1_[4][2], b3_[4][2];
                #pragma unroll
                for (int ni = 0; ni < 4; ni++) {
                    uint32_t bb1 = bs + 2 * PS + bp + boff + ni * (8 * SROW) + ko;
                    uint32_t bb3 = bs + 4 * PS + bp + boff + ni * (8 * SROW) + ko;
                    b1_[ni][0] = lds32(bb1); b1_[ni][1] = lds32(bb1 + 16);
                    b3_[ni][0] = lds32(bb3); b3_[ni][1] = lds32(bb3 + 16);
                }
                #pragma unroll
                for (int mi = 0; mi < 4; mi++)
                    #pragma unroll
                    for (int ni = 0; ni < 4; ni++) {
                        mma16816(c1[mi][ni], a_[mi][0], a_[mi][1], a_[mi][2], a_[mi][3],
                                 b1_[ni][0], b1_[ni][1]);
                        mma16816(c3[mi][ni], a_[mi][0], a_[mi][1], a_[mi][2], a_[mi][3],
                                 b3_[ni][0], b3_[ni][1]);
                    }
            }
        }
    }

    // epilogue: act = silu(h1)*h3 -> bf16 hi/lo
    #pragma unroll
    for (int mi = 0; mi < 4; mi++) {
        int r0 = m0 + wm + mi * 16 + g;
        #pragma unroll
        for (int ni = 0; ni < 4; ni++) {
            int cb = n0 + wn + ni * 8 + tg * 2;
            float h1a = c1[mi][ni][0], h1b = c1[mi][ni][1];
            float v0 = h1a / (1.f + expf(-h1a)) * c3[mi][ni][0];
            float v1 = h1b / (1.f + expf(-h1b)) * c3[mi][ni][1];
            float h1c = c1[mi][ni][2], h1d = c1[mi][ni][3];
            float v2 = h1c / (1.f + expf(-h1c)) * c3[mi][ni][2];
            float v3 = h1d / (1.f + expf(-h1d)) * c3[mi][ni][3];
            uint32_t h, l;
            size_t o0 = ((size_t)e * CAP + r0) * IDIM + cb;
            split2(v0, v1, h, l);
            *(uint32_t*)(g_acth + o0) = h;
            *(uint32_t*)(g_actl + o0) = l;
            size_t o1 = ((size_t)e * CAP + r0 + 8) * IDIM + cb;
            split2(v2, v3, h, l);
            *(uint32_t*)(g_acth + o1) = h;
            *(uint32_t*)(g_actl + o1) = l;
        }
    }
}

// ---------------- GEMM2: y = act @ w2^T, 3-pass bf16 mma ----------------
#define G2_PLANES 4
#define G2_STAGE  (G2_PLANES * PS)   // 40960
#define G2_SMEM   (3 * G2_STAGE)     // 122880

__global__ __launch_bounds__(256) void gemm2_mma(void) {
    int e   = blockIdx.z;
    int cnt = g_cnt[e];
    int m0  = blockIdx.y * 128;
    if (m0 >= cnt) return;
    int n0  = blockIdx.x * 128;

    extern __shared__ char sm[];
    uint32_t sb = smem_u32(sm);
    int tid = threadIdx.x, lane = tid & 31, wid = tid >> 5;
    int wm = (wid & 1) * 64, wn = (wid >> 1) * 32;
    int g = lane >> 2, tg = lane & 3;

    const __nv_bfloat16* srcs[G2_PLANES] = {
        g_acth + ((size_t)e * CAP + m0) * IDIM,
        g_actl + ((size_t)e * CAP + m0) * IDIM,
        g_w2h  + ((size_t)e * H_  + n0) * IDIM,
        g_w2l  + ((size_t)e * H_  + n0) * IDIM
    };
    int  lrow = tid >> 1;
    int  lcb  = (tid & 1) * 2;
    uint32_t ldst = lrow * SROW + lcb * 16;

    #pragma unroll
    for (int st = 0; st < 2; st++) {
        uint32_t s = sb + st * G2_STAGE + ldst;
        int k0 = st * 32 + lcb * 8;
        #pragma unroll
        for (int p = 0; p < G2_PLANES; p++) {
            const __nv_bfloat16* gp = srcs[p] + (size_t)lrow * IDIM + k0;
            cp16(s + p * PS,      gp);
            cp16(s + p * PS + 16, gp + 8);
        }
        cp_commit();
    }

    float cc[4][4][4] = {};
    uint32_t aoff = (wm + g) * SROW + tg * 4;
    uint32_t boff = (wn + g) * SROW + tg * 4;

    const int NK = IDIM / 32;  // 24
    for (int kt = 0; kt < NK; kt++) {
        cp_wait1();
        __syncthreads();
        if (kt + 2 < NK) {
            uint32_t s = sb + ((kt + 2) % 3) * G2_STAGE + ldst;
            int k0 = (kt + 2) * 32 + lcb * 8;
            #pragma unroll
            for (int p = 0; p < G2_PLANES; p++) {
                const __nv_bfloat16* gp = srcs[p] + (size_t)lrow * IDIM + k0;
                cp16(s + p * PS,      gp);
                cp16(s + p * PS + 16, gp + 8);
            }
        }
        cp_commit();

        uint32_t bs = sb + (kt % 3) * G2_STAGE;
        #pragma unroll
        for (int kb = 0; kb < 2; kb++) {
            uint32_t ko = kb * 32;
            #pragma unroll
            for (int p = 0; p < 3; p++) {
                uint32_t ap = (p == 1) ? PS : 0;
                uint32_t bp = (p == 2) ? PS : 0;
                uint32_t a_[4][4];
                #pragma unroll
                for (int mi = 0; mi < 4; mi++) {
                    uint32_t ba = bs + ap + aoff + mi * (16 * SROW) + ko;
                    a_[mi][0] = lds32(ba);
                    a_[mi][1] = lds32(ba + 8 * SROW);
                    a_[mi][2] = lds32(ba + 16);
                    a_[mi][3] = lds32(ba + 8 * SROW + 16);
                }
                uint32_t b_[4][2];
                #pragma unroll
                for (int ni = 0; ni < 4; ni++) {
                    uint32_t bb = bs + 2 * PS + bp + boff + ni * (8 * SROW) + ko;
                    b_[ni][0] = lds32(bb); b_[ni][1] = lds32(bb + 16);
                }
                #pragma unroll
                for (int mi = 0; mi < 4; mi++)
                    #pragma unroll
                    for (int ni = 0; ni < 4; ni++)
                        mma16816(cc[mi][ni], a_[mi][0], a_[mi][1], a_[mi][2], a_[mi][3],
                                 b_[ni][0], b_[ni][1]);
            }
        }
    }

    #pragma unroll
    for (int mi = 0; mi < 4; mi++) {
        int r0 = m0 + wm + mi * 16 + g;
        #pragma unroll
        for (int ni = 0; ni < 4; ni++) {
            int cb = n0 + wn + ni * 8 + tg * 2;
            *(float2*)(g_y + ((size_t)e * CAP + r0) * H_ + cb) =
                make_float2(cc[mi][ni][0], cc[mi][ni][1]);
            *(float2*)(g_y + ((size_t)e * CAP + r0 + 8) * H_ + cb) =
                make_float2(cc[mi][ni][2], cc[mi][ni][3]);
        }
    }
}

// ---------------- combine ----------------
__global__ void combine_kernel(float* __restrict__ out) {
    int t = blockIdx.x;
    int i = threadIdx.x;
    float4 acc = make_float4(0.f, 0.f, 0.f, 0.f);
    #pragma unroll
    for (int k = 0; k < KSEL; k++) {
        int a = t * KSEL + k;
        int slot = g_slot[a];
        if (slot < 0) continue;
        int e = g_expi[a];
        float w = g_gw[a];
        const float4* yr = (const float4*)(g_y + ((size_t)e * CAP + slot) * H_);
        float4 v = yr[i];
        acc.x += w * v.x; acc.y += w * v.y; acc.z += w * v.z; acc.w += w * v.w;
    }
    ((float4*)(out + (size_t)t * H_))[i] = acc;
}

// ---------------- launch ----------------
extern "C" void kernel_launch(void* const* d_in, const int* in_sizes, int n_in,
                              void* d_out, int out_size) {
    (void)in_sizes; (void)n_in; (void)out_size;
    const float* x      = (const float*)d_in[0];
    const float* gate_w = (const float*)d_in[1];
    const float* w1     = (const float*)d_in[2];
    const float* w3     = (const float*)d_in[3];
    const float* w2     = (const float*)d_in[4];
    const float* bias   = (const float*)d_in[5];
    float*       out    = (float*)d_out;

    cudaFuncSetAttribute(gemm1_mma, cudaFuncAttributeMaxDynamicSharedMemorySize, G1_SMEM);
    cudaFuncSetAttribute(gemm2_mma, cudaFuncAttributeMaxDynamicSharedMemorySize, G2_SMEM);

    // resolve device-global addresses for the cvt kernels
    void *p_w1h, *p_w1l, *p_w3h, *p_w3l, *p_w2h, *p_w2l;
    cudaGetSymbolAddress(&p_w1h, g_w1h);
    cudaGetSymbolAddress(&p_w1l, g_w1l);
    cudaGetSymbolAddress(&p_w3h, g_w3h);
    cudaGetSymbolAddress(&p_w3l, g_w3l);
    cudaGetSymbolAddress(&p_w2h, g_w2h);
    cudaGetSymbolAddress(&p_w2l, g_w2l);

    const int n4 = E_ * IDIM * H_ / 4;  // per-weight float4 count
    cvt_kernel<<<4096, 256>>>((const float4*)w1, (uint2*)p_w1h, (uint2*)p_w1l, n4);
    cvt_kernel<<<4096, 256>>>((const float4*)w3, (uint2*)p_w3h, (uint2*)p_w3l, n4);
    cvt_kernel<<<4096, 256>>>((const float4*)w2, (uint2*)p_w2h, (uint2*)p_w2l, n4);

    router_kernel<<<T_, 128>>>(x, gate_w, bias);
    slot_kernel<<<E_, 1024>>>();
    gather_kernel<<<dim3(CAP, E_), 256>>>(x);
    gemm1_mma<<<dim3(IDIM / 128, CAP / 128, E_), 256, G1_SMEM>>>();
    gemm2_mma<<<dim3(H_ / 128, CAP / 128, E_), 256, G2_SMEM>>>();
    combine_kernel<<<T_, 256>>>(out);
}